// round 17
// baseline (speedup 1.0000x reference)
#include <cuda_runtime.h>
#include <cuda_bf16.h>

// FastSpeech2 hard duration-based frame->token scalar averaging.
//   d_in[0] frame_scalar      float32 [B, 8192]
//   d_in[1] duration          float32 [B, 1024]
//   d_in[2] frame_scalar_len  int32   [B]
//   d_in[3] duration_len      int32   [B]
// Output: token_scalar float32 [B, 1024] (+ optional duration_len as f32 [B]).
//
// R16 = champion R14 (bounded reads, SPEC=4 cp.async speculation, scan-free
// direct gather) with the gather's serial scalar loop replaced by
// head(<=3 scalar) + LDS.128 middle(<=4 float4) + tail(<=3 scalar).
// Adds remain in ascending index order -> bit-identical results.
// Plus max smem carveout to fit 6 CTAs/SM (33KB each).

#define TFR 8192
#define TTK 1024
#define NTHREADS 256
#define CHT 4                    // tokens per thread
#define NWARPS (NTHREADS / 32)
#define SPEC_BLOCKS 4            // speculative 1024-float blocks

__global__ __launch_bounds__(NTHREADS)
void fs2_dur_avg_kernel(const float* __restrict__ frame_scalar,
                        const float* __restrict__ duration,
                        const int*   __restrict__ frame_scalar_len,
                        const int*   __restrict__ duration_len,
                        float*       __restrict__ out,
                        int B, int write_extra)
{
    __shared__ __align__(16) float s_buf[TFR];   // staged frame row (plain)
    __shared__ float s_dwsum[NWARPS];            // duration warp totals

    const int row  = blockIdx.x;
    const int tid  = threadIdx.x;
    const int lane = tid & 31;
    const int wid  = tid >> 5;

    const float* fsrow = frame_scalar + (size_t)row * TFR;
    const unsigned smb = (unsigned)__cvta_generic_to_shared(s_buf);

    // ---- speculative cp.async of first SPEC_BLOCKS frame blocks ----------
    // (fire-and-forget; overlaps the duration load + cumsum below)
    #pragma unroll
    for (int k = 0; k < SPEC_BLOCKS; k++) {
        const int idx = (k << 10) + (tid << 2);          // k*1024 + tid*4
        asm volatile("cp.async.cg.shared.global [%0], [%1], 16;\n"
                     :: "r"(smb + idx * 4), "l"(fsrow + idx));
    }
    asm volatile("cp.async.commit_group;\n");

    // ---- duration load + per-thread/warp cumsum ---------------------------
    const float4 d4 = reinterpret_cast<const float4*>(
                          duration + (size_t)row * TTK)[tid];
    const int   dl = duration_len[row];
    const float fl = (float)frame_scalar_len[row];

    float dv[CHT], p[CHT], d_excl;
    {
        const float din[CHT] = {d4.x, d4.y, d4.z, d4.w};
        const int jbase = tid * CHT;
        #pragma unroll
        for (int k = 0; k < CHT; k++) {
            // round half-to-even (jnp.round), clamp >=0, zero past dlen
            const float r = fmaxf(rintf(din[k]), 0.0f);
            dv[k] = (jbase + k < dl) ? r : 0.0f;
        }
        float run = 0.0f;
        #pragma unroll
        for (int k = 0; k < CHT; k++) { run += dv[k]; p[k] = run; }
        float incl = run;
        #pragma unroll
        for (int d = 1; d < 32; d <<= 1) {
            const float t = __shfl_up_sync(0xffffffffu, incl, d);
            if (lane >= d) incl += t;
        }
        if (lane == 31) s_dwsum[wid] = incl;
        d_excl = incl - run;                 // exclusive offset within warp
    }
    __syncthreads();                         // s_dwsum visible

    // Total duration + this thread's cross-warp offset (ascending order,
    // exact integer-valued sums -> deterministic).
    float dur_total = 0.0f;
    float doff = d_excl;
    #pragma unroll
    for (int i = 0; i < NWARPS; i++) {
        const float v = s_dwsum[i];
        dur_total += v;
        if (i < wid) doff += v;
    }

    // Frames actually referenced: indices < needed.
    const int needed = (int)fminf(dur_total, fl);
    const int kmax   = (needed + 1023) >> 10;        // 1024-float blocks

    // ---- stage remaining needed blocks (cp.async, all in flight) ----------
    for (int k = SPEC_BLOCKS; k < kmax; k++) {
        const int idx = (k << 10) + (tid << 2);
        asm volatile("cp.async.cg.shared.global [%0], [%1], 16;\n"
                     :: "r"(smb + idx * 4), "l"(fsrow + idx));
    }
    asm volatile("cp.async.commit_group;\n");
    asm volatile("cp.async.wait_group 0;\n");        // all staging complete
    __syncthreads();

    // ---- gather: direct segment sums, vectorized (order-preserving) -------
    {
        float4 res;
        float* rp = reinterpret_cast<float*>(&res);
        #pragma unroll
        for (int k = 0; k < CHT; k++) {
            const float cend_raw   = doff + p[k];       // cumsum thru token j
            const float cstart_raw = cend_raw - dv[k];  // cumsum thru j-1
            const float endf   = fminf(cend_raw, fl);
            const float startf = fminf(cstart_raw, fl);
            const float dlen_f = endf - startf;         // exact int-valued
            const int e = (int)endf;                    // e <= needed
            const int s = (int)startf;

            float sum = 0.0f;
            int i = s;
            // head: scalar up to 16B alignment (<=3 iters)
            const int ahead = (s + 3) & ~3;
            const int head_end = (ahead < e) ? ahead : e;
            while (i < head_end) sum += s_buf[i++];
            // middle: LDS.128 (<=4 iters, adds stay in ascending order)
            while (i + 4 <= e) {
                const float4 v = *reinterpret_cast<const float4*>(&s_buf[i]);
                sum += v.x; sum += v.y; sum += v.z; sum += v.w;
                i += 4;
            }
            // tail: scalar (<=3 iters)
            while (i < e) sum += s_buf[i++];

            rp[k] = (dlen_f > 0.0f) ? sum / fmaxf(dlen_f, 1.0f) : 0.0f;
        }
        reinterpret_cast<float4*>(out + (size_t)row * TTK)[tid] = res;
    }

    // Optional second tuple output: duration_len (numeric cast to f32).
    if (write_extra && tid == 0)
        out[(size_t)B * TTK + row] = (float)dl;
}

extern "C" void kernel_launch(void* const* d_in, const int* in_sizes, int n_in,
                              void* d_out, int out_size) {
    const float* frame_scalar     = (const float*)d_in[0];
    const float* duration         = (const float*)d_in[1];
    const int*   frame_scalar_len = (const int*)d_in[2];
    const int*   duration_len     = (const int*)d_in[3];
    float* out = (float*)d_out;

    const int B = in_sizes[2];                       // [B] int32
    const int write_extra = (out_size > B * TTK) ? 1 : 0;

    // Ask for the largest smem carveout so 33KB/CTA fits 6 CTAs/SM.
    static int carveout_set = 0;
    if (!carveout_set) {
        cudaFuncSetAttribute(fs2_dur_avg_kernel,
                             cudaFuncAttributePreferredSharedMemoryCarveout, 100);
        carveout_set = 1;
    }

    fs2_dur_avg_kernel<<<B, NTHREADS>>>(frame_scalar, duration,
                                        frame_scalar_len, duration_len,
                                        out, B, write_extra);
}